// round 1
// baseline (speedup 1.0000x reference)
#include <cuda_runtime.h>
#include <cuda_bf16.h>
#include <cstddef>

// ---------------------------------------------------------------------------
// Problem constants
// ---------------------------------------------------------------------------
#define B_SZ   4
#define C_IN   512
#define TD3    1536          // 3*512
#define HH     64
#define WW     64
#define NPIX   4096          // 64*64
#define NGRP   192           // pw groups
#define NHEAD  128           // 3072 / 24
#define EPS_ATT 1e-15f
#define EPS_BN  1e-5f

// ---------------------------------------------------------------------------
// Scratch (device globals; no allocation allowed)
// ---------------------------------------------------------------------------
__device__ float g_qkv[(size_t)B_SZ * TD3 * NPIX];   // 96 MB
__device__ float g_y  [(size_t)B_SZ * TD3 * NPIX];   // 96 MB
__device__ float g_att[(size_t)B_SZ * 1024 * NPIX];  // 64 MB

// ---------------------------------------------------------------------------
// SGEMM: C[b] = A(MxK, row-major, shared) * B[b](KxN, row-major)
// 128x128 block tile, K-tile 8, 256 threads, 8x8 per-thread micro-tile.
// EPI=true fuses the batchnorm affine (per output row/channel).
// Requires M%128==0, N%128==0, K%8==0 (true for all our calls).
// ---------------------------------------------------------------------------
template <bool EPI>
__global__ __launch_bounds__(256, 2)
void sgemm_kernel(const float* __restrict__ A, const float* __restrict__ Bg,
                  float* __restrict__ Cg, int M, int N, int K,
                  const float* __restrict__ gamma, const float* __restrict__ beta,
                  const float* __restrict__ mean,  const float* __restrict__ var)
{
    __shared__ float As[8][128];
    __shared__ float Bs[8][128];

    const int tid = threadIdx.x;
    const int m0  = blockIdx.y * 128;
    const int n0  = blockIdx.x * 128;
    const float* Bp = Bg + (size_t)blockIdx.z * K * N;
    float*       Cp = Cg + (size_t)blockIdx.z * M * N;

    const int arow = tid >> 1;           // 0..127
    const int acol = (tid & 1) << 2;     // 0 or 4
    const int brow = tid >> 5;           // 0..7
    const int bcol = (tid & 31) << 2;    // 0..124
    const int tx   = tid & 15;
    const int ty   = tid >> 4;

    float acc[8][8];
#pragma unroll
    for (int i = 0; i < 8; i++)
#pragma unroll
        for (int j = 0; j < 8; j++) acc[i][j] = 0.f;

    for (int k0 = 0; k0 < K; k0 += 8) {
        float4 av = *(const float4*)(A + (size_t)(m0 + arow) * K + k0 + acol);
        As[acol + 0][arow] = av.x;
        As[acol + 1][arow] = av.y;
        As[acol + 2][arow] = av.z;
        As[acol + 3][arow] = av.w;
        *(float4*)&Bs[brow][bcol] =
            *(const float4*)(Bp + (size_t)(k0 + brow) * N + n0 + bcol);
        __syncthreads();

#pragma unroll
        for (int k = 0; k < 8; k++) {
            float4 a0 = *(const float4*)&As[k][ty * 8];
            float4 a1 = *(const float4*)&As[k][ty * 8 + 4];
            float4 b0 = *(const float4*)&Bs[k][tx * 8];
            float4 b1 = *(const float4*)&Bs[k][tx * 8 + 4];
            float a[8] = {a0.x, a0.y, a0.z, a0.w, a1.x, a1.y, a1.z, a1.w};
            float b[8] = {b0.x, b0.y, b0.z, b0.w, b1.x, b1.y, b1.z, b1.w};
#pragma unroll
            for (int i = 0; i < 8; i++)
#pragma unroll
                for (int j = 0; j < 8; j++) acc[i][j] += a[i] * b[j];
        }
        __syncthreads();
    }

#pragma unroll
    for (int i = 0; i < 8; i++) {
        int o = m0 + ty * 8 + i;
        float s = 1.f, t = 0.f;
        if (EPI) {
            float iv = rsqrtf(var[o] + EPS_BN);
            s = gamma[o] * iv;
            t = beta[o] - mean[o] * s;
        }
        float* crow = Cp + (size_t)o * N + n0 + tx * 8;
        float4 r0, r1;
        if (EPI) {
            r0 = make_float4(acc[i][0]*s+t, acc[i][1]*s+t, acc[i][2]*s+t, acc[i][3]*s+t);
            r1 = make_float4(acc[i][4]*s+t, acc[i][5]*s+t, acc[i][6]*s+t, acc[i][7]*s+t);
        } else {
            r0 = make_float4(acc[i][0], acc[i][1], acc[i][2], acc[i][3]);
            r1 = make_float4(acc[i][4], acc[i][5], acc[i][6], acc[i][7]);
        }
        *(float4*)(crow)     = r0;
        *(float4*)(crow + 4) = r1;
    }
}

// ---------------------------------------------------------------------------
// Fused depthwise 5x5 (pad 2) + grouped 8x8 pointwise.
// One block per (batch, group, 32x8 pixel tile). Group = 8 consecutive channels.
// ---------------------------------------------------------------------------
__global__ __launch_bounds__(256)
void dwpw_kernel(const float* __restrict__ qkv, const float* __restrict__ w_dw,
                 const float* __restrict__ w_pw, float* __restrict__ y)
{
    __shared__ float tile[8][12][36];  // 8 ch x (8+4) rows x (32+4) cols
    __shared__ float wdw[8][25];
    __shared__ float wpw[64];

    const int b   = blockIdx.z / NGRP;
    const int g   = blockIdx.z % NGRP;
    const int ch0 = g * 8;
    const int w0  = blockIdx.x * 32;
    const int h0  = blockIdx.y * 8;
    const int tid = threadIdx.y * 32 + threadIdx.x;

    for (int i = tid; i < 200; i += 256)
        wdw[i / 25][i % 25] = w_dw[(ch0 + i / 25) * 25 + i % 25];
    if (tid < 64) wpw[tid] = w_pw[g * 64 + tid];

    const float* base = qkv + ((size_t)b * TD3 + ch0) * NPIX;
    for (int i = tid; i < 8 * 12 * 36; i += 256) {
        int c  = i / 432;
        int r  = (i % 432) / 36;
        int cc = i % 36;
        int gh = h0 - 2 + r;
        int gw = w0 - 2 + cc;
        float v = 0.f;
        if (gh >= 0 && gh < HH && gw >= 0 && gw < WW)
            v = base[(size_t)c * NPIX + gh * WW + gw];
        tile[c][r][cc] = v;
    }
    __syncthreads();

    const int tx = threadIdx.x, ty = threadIdx.y;
    float dw[8];
#pragma unroll
    for (int c = 0; c < 8; c++) {
        float s = 0.f;
#pragma unroll
        for (int i = 0; i < 5; i++)
#pragma unroll
            for (int j = 0; j < 5; j++)
                s += tile[c][ty + i][tx + j] * wdw[c][i * 5 + j];
        dw[c] = s;
    }

    const int n = (h0 + ty) * WW + (w0 + tx);
    float* obase = y + ((size_t)b * TD3 + ch0) * NPIX + n;
#pragma unroll
    for (int o = 0; o < 8; o++) {
        float s = 0.f;
#pragma unroll
        for (int i = 0; i < 8; i++) s += dw[i] * wpw[o * 8 + i];
        obase[(size_t)o * NPIX] = s;
    }
}

// ---------------------------------------------------------------------------
// Linear attention. One block per (batch, head). 256 threads.
// rows 0..7 = q (relu), 8..15 = k (relu), 16..23 = v; extra ones-row for denom.
// heads 0..63 read from qkv, 64..127 from y.
// ---------------------------------------------------------------------------
__global__ __launch_bounds__(256)
void attn_kernel(const float* __restrict__ qkv, const float* __restrict__ y,
                 float* __restrict__ att)
{
    const int bh = blockIdx.x;
    const int b  = bh / NHEAD;
    const int h  = bh % NHEAD;
    const int tid = threadIdx.x;

    const float* base = (h < 64)
        ? qkv + ((size_t)b * TD3 + h * 24) * NPIX
        : y   + ((size_t)b * TD3 + (h - 64) * 24) * NPIX;

    // Phase 1: vk[r][e], r=0..7 from v rows, r=8 = ones row (sum of k).
    float acc[72];
#pragma unroll
    for (int i = 0; i < 72; i++) acc[i] = 0.f;

    for (int n = tid; n < NPIX; n += 256) {
        float kk[8], vv[8];
#pragma unroll
        for (int e = 0; e < 8; e++) kk[e] = fmaxf(base[(size_t)(8 + e) * NPIX + n], 0.f);
#pragma unroll
        for (int d = 0; d < 8; d++) vv[d] = base[(size_t)(16 + d) * NPIX + n];
#pragma unroll
        for (int d = 0; d < 8; d++)
#pragma unroll
            for (int e = 0; e < 8; e++) acc[d * 8 + e] += vv[d] * kk[e];
#pragma unroll
        for (int e = 0; e < 8; e++) acc[64 + e] += kk[e];
    }

    __shared__ float red[8][72];
    __shared__ float vk_s[72];
    const int lane = tid & 31, wid = tid >> 5;
#pragma unroll
    for (int i = 0; i < 72; i++) {
        float v = acc[i];
        v += __shfl_down_sync(0xffffffffu, v, 16);
        v += __shfl_down_sync(0xffffffffu, v, 8);
        v += __shfl_down_sync(0xffffffffu, v, 4);
        v += __shfl_down_sync(0xffffffffu, v, 2);
        v += __shfl_down_sync(0xffffffffu, v, 1);
        if (lane == 0) red[wid][i] = v;
    }
    __syncthreads();
    if (tid < 72) {
        float s = 0.f;
#pragma unroll
        for (int w = 0; w < 8; w++) s += red[w][tid];
        vk_s[tid] = s;
    }
    __syncthreads();

    // Phase 2: out[d][n] = (sum_e vk[d][e] q[e][n]) / (sum_e vk[8][e] q[e][n] + eps)
    float vk[72];
#pragma unroll
    for (int i = 0; i < 72; i++) vk[i] = vk_s[i];

    float* obase = att + ((size_t)b * 1024 + h * 8) * NPIX;
    for (int n = tid; n < NPIX; n += 256) {
        float q[8];
#pragma unroll
        for (int e = 0; e < 8; e++) q[e] = fmaxf(base[(size_t)e * NPIX + n], 0.f);
        float den = 0.f;
#pragma unroll
        for (int e = 0; e < 8; e++) den += vk[64 + e] * q[e];
        float inv = 1.f / (den + EPS_ATT);
#pragma unroll
        for (int d = 0; d < 8; d++) {
            float num = 0.f;
#pragma unroll
            for (int e = 0; e < 8; e++) num += vk[d * 8 + e] * q[e];
            obase[(size_t)d * NPIX + n] = num * inv;
        }
    }
}

// ---------------------------------------------------------------------------
// Launch
// ---------------------------------------------------------------------------
extern "C" void kernel_launch(void* const* d_in, const int* in_sizes, int n_in,
                              void* d_out, int out_size)
{
    const float* x      = (const float*)d_in[0];
    const float* w_qkv  = (const float*)d_in[1];
    const float* w_dw   = (const float*)d_in[2];
    const float* w_pw   = (const float*)d_in[3];
    const float* w_proj = (const float*)d_in[4];
    const float* gamma  = (const float*)d_in[5];
    const float* beta   = (const float*)d_in[6];
    const float* mean   = (const float*)d_in[7];
    const float* var    = (const float*)d_in[8];
    float* out = (float*)d_out;

    float *qkv, *yb, *att;
    cudaGetSymbolAddress((void**)&qkv, g_qkv);
    cudaGetSymbolAddress((void**)&yb,  g_y);
    cudaGetSymbolAddress((void**)&att, g_att);

    // 1) qkv = w_qkv @ x      (M=1536, K=512, N=4096, per batch)
    sgemm_kernel<false><<<dim3(NPIX / 128, TD3 / 128, B_SZ), 256>>>(
        w_qkv, x, qkv, TD3, NPIX, C_IN, nullptr, nullptr, nullptr, nullptr);

    // 2) y = grouped-pw(dwconv5x5(qkv))
    dwpw_kernel<<<dim3(WW / 32, HH / 8, B_SZ * NGRP), dim3(32, 8)>>>(
        qkv, w_dw, w_pw, yb);

    // 3) linear attention -> att (B,1024,4096)
    attn_kernel<<<B_SZ * NHEAD, 256>>>(qkv, yb, att);

    // 4) out = BN(w_proj @ att)   (M=512, K=1024, N=4096, per batch)
    sgemm_kernel<true><<<dim3(NPIX / 128, 512 / 128, B_SZ), 256>>>(
        w_proj, att, out, 512, NPIX, 1024, gamma, beta, mean, var);
}

// round 2
// speedup vs baseline: 2.1097x; 2.1097x over previous
#include <cuda_runtime.h>
#include <cuda_bf16.h>
#include <cstdint>
#include <cstddef>

// ---------------------------------------------------------------------------
// Problem constants
// ---------------------------------------------------------------------------
#define B_SZ   4
#define C_IN   512
#define TD3    1536          // 3*512
#define HH     64
#define WW     64
#define NPIX   4096          // 64*64
#define NGRP   192
#define NHEAD  128
#define EPS_ATT 1e-15f
#define EPS_BN  1e-5f

// ---------------------------------------------------------------------------
// Scratch (device globals; no allocation allowed)
// ---------------------------------------------------------------------------
__device__ float          g_qkv [(size_t)B_SZ * TD3 * NPIX];     // 96 MB fp32
__device__ float          g_y   [(size_t)B_SZ * TD3 * NPIX];     // 96 MB fp32
__device__ __nv_bfloat16  g_xh  [(size_t)B_SZ * C_IN * NPIX];    // 16.8 MB
__device__ __nv_bfloat16  g_xl  [(size_t)B_SZ * C_IN * NPIX];
__device__ __nv_bfloat16  g_atth[(size_t)B_SZ * 1024 * NPIX];    // 32 MB
__device__ __nv_bfloat16  g_attl[(size_t)B_SZ * 1024 * NPIX];
__device__ __nv_bfloat16  g_wqh [TD3 * C_IN];
__device__ __nv_bfloat16  g_wql [TD3 * C_IN];
__device__ __nv_bfloat16  g_wph [512 * 1024];
__device__ __nv_bfloat16  g_wpl [512 * 1024];

// ---------------------------------------------------------------------------
// fp32 -> bf16 hi/lo split (vectorized x4)
// ---------------------------------------------------------------------------
__global__ void split_kernel(const float* __restrict__ in,
                             __nv_bfloat16* __restrict__ h,
                             __nv_bfloat16* __restrict__ l, int n4)
{
    int i = blockIdx.x * 256 + threadIdx.x;
    if (i >= n4) return;
    float4 v = ((const float4*)in)[i];
    __nv_bfloat16 h0 = __float2bfloat16(v.x);
    __nv_bfloat16 h1 = __float2bfloat16(v.y);
    __nv_bfloat16 h2 = __float2bfloat16(v.z);
    __nv_bfloat16 h3 = __float2bfloat16(v.w);
    __nv_bfloat162 hp0 = __nv_bfloat162(h0, h1), hp1 = __nv_bfloat162(h2, h3);
    __nv_bfloat162 lp0 = __nv_bfloat162(__float2bfloat16(v.x - __bfloat162float(h0)),
                                        __float2bfloat16(v.y - __bfloat162float(h1)));
    __nv_bfloat162 lp1 = __nv_bfloat162(__float2bfloat16(v.z - __bfloat162float(h2)),
                                        __float2bfloat16(v.w - __bfloat162float(h3)));
    ((__nv_bfloat162*)h)[i * 2]     = hp0;
    ((__nv_bfloat162*)h)[i * 2 + 1] = hp1;
    ((__nv_bfloat162*)l)[i * 2]     = lp0;
    ((__nv_bfloat162*)l)[i * 2 + 1] = lp1;
}

// ---------------------------------------------------------------------------
// mma helpers
// ---------------------------------------------------------------------------
__device__ __forceinline__ void ldsm_x4(uint32_t* r, uint32_t addr) {
    asm volatile("ldmatrix.sync.aligned.m8n8.x4.shared.b16 {%0,%1,%2,%3}, [%4];"
        : "=r"(r[0]), "=r"(r[1]), "=r"(r[2]), "=r"(r[3]) : "r"(addr));
}
__device__ __forceinline__ void ldsm_x4_t(uint32_t* r, uint32_t addr) {
    asm volatile("ldmatrix.sync.aligned.m8n8.x4.trans.shared.b16 {%0,%1,%2,%3}, [%4];"
        : "=r"(r[0]), "=r"(r[1]), "=r"(r[2]), "=r"(r[3]) : "r"(addr));
}
__device__ __forceinline__ void mma_bf16(float* c, const uint32_t* a, const uint32_t* b) {
    asm volatile("mma.sync.aligned.m16n8k16.row.col.f32.bf16.bf16.f32 "
        "{%0,%1,%2,%3}, {%4,%5,%6,%7}, {%8,%9}, {%0,%1,%2,%3};"
        : "+f"(c[0]), "+f"(c[1]), "+f"(c[2]), "+f"(c[3])
        : "r"(a[0]), "r"(a[1]), "r"(a[2]), "r"(a[3]), "r"(b[0]), "r"(b[1]));
}

// A tile smem: [128 rows][32 k] bf16, 16B chunk swizzled
__device__ __forceinline__ uint32_t swA(int row, int ch) {
    return (uint32_t)(row * 64 + ((ch ^ ((row >> 1) & 3)) << 4));
}
// B tile smem: [32 k][128 n] bf16, 16B chunk swizzled
__device__ __forceinline__ uint32_t swB(int k, int ch) {
    return (uint32_t)(k * 256 + ((ch ^ (k & 7)) << 4));
}

// ---------------------------------------------------------------------------
// bf16-split tensor-core GEMM:
//   C[b] = (Ah+Al)(MxK) * (Bh+Bl)[b](KxN)  (3-term Markidis)
// A row-major, shared across batch; B row-major per batch; C fp32 row-major.
// Block 128x128, K-tile 32, 256 threads (8 warps = 2x4, warp tile 64x32).
// EPI fuses the batchnorm affine.
// ---------------------------------------------------------------------------
template <bool EPI>
__global__ __launch_bounds__(256, 1)
void mma_gemm(const __nv_bfloat16* __restrict__ Ah, const __nv_bfloat16* __restrict__ Al,
              const __nv_bfloat16* __restrict__ Bhg, const __nv_bfloat16* __restrict__ Blg,
              float* __restrict__ Cg, int M, int N, int K,
              const float* __restrict__ gamma, const float* __restrict__ beta,
              const float* __restrict__ mean,  const float* __restrict__ var)
{
    __shared__ __align__(16) __nv_bfloat16 sAh[128 * 32];
    __shared__ __align__(16) __nv_bfloat16 sAl[128 * 32];
    __shared__ __align__(16) __nv_bfloat16 sBh[32 * 128];
    __shared__ __align__(16) __nv_bfloat16 sBl[32 * 128];

    const int tid  = threadIdx.x;
    const int lane = tid & 31;
    const int wid  = tid >> 5;
    const int warp_m = wid >> 2;   // 0..1  (64 rows)
    const int warp_n = wid & 3;    // 0..3  (32 cols)
    const int m0 = blockIdx.y * 128;
    const int n0 = blockIdx.x * 128;

    const __nv_bfloat16* Bh = Bhg + (size_t)blockIdx.z * K * N;
    const __nv_bfloat16* Bl = Blg + (size_t)blockIdx.z * K * N;
    float* Cp = Cg + (size_t)blockIdx.z * M * N;

    const uint32_t aAh = (uint32_t)__cvta_generic_to_shared(sAh);
    const uint32_t aAl = (uint32_t)__cvta_generic_to_shared(sAl);
    const uint32_t aBh = (uint32_t)__cvta_generic_to_shared(sBh);
    const uint32_t aBl = (uint32_t)__cvta_generic_to_shared(sBl);

    // gmem->reg staging indices
    const int arow = tid >> 2, ach = tid & 3;    // A: 2 chunks (rows +0, +64)
    const int bk   = tid >> 4, bch = tid & 15;   // B: 2 chunks (k +0, +16)

    float acc[4][4][4];
#pragma unroll
    for (int i = 0; i < 4; i++)
#pragma unroll
        for (int j = 0; j < 4; j++)
#pragma unroll
            for (int r = 0; r < 4; r++) acc[i][j][r] = 0.f;

    uint4 pah[2], pal[2], pbh[2], pbl[2];

    auto fetch = [&](int kt) {
#pragma unroll
        for (int i = 0; i < 2; i++) {
            size_t aoff = (size_t)(m0 + arow + i * 64) * K + kt * 32 + ach * 8;
            pah[i] = *(const uint4*)(Ah + aoff);
            pal[i] = *(const uint4*)(Al + aoff);
            size_t boff = (size_t)(kt * 32 + bk + i * 16) * N + n0 + bch * 8;
            pbh[i] = *(const uint4*)(Bh + boff);
            pbl[i] = *(const uint4*)(Bl + boff);
        }
    };
    auto store = [&]() {
#pragma unroll
        for (int i = 0; i < 2; i++) {
            uint32_t ao = swA(arow + i * 64, ach);
            *(uint4*)((char*)sAh + ao) = pah[i];
            *(uint4*)((char*)sAl + ao) = pal[i];
            uint32_t bo = swB(bk + i * 16, bch);
            *(uint4*)((char*)sBh + bo) = pbh[i];
            *(uint4*)((char*)sBl + bo) = pbl[i];
        }
    };

    const int nkt = K / 32;
    fetch(0);
    store();
    __syncthreads();

    for (int kt = 0; kt < nkt; ++kt) {
        if (kt + 1 < nkt) fetch(kt + 1);

#pragma unroll
        for (int kk = 0; kk < 2; ++kk) {
            const int kcol = kk * 16;
            uint32_t ah[4][4], al[4][4], bh[2][4], bl[2][4];
#pragma unroll
            for (int mf = 0; mf < 4; mf++) {
                int row = warp_m * 64 + mf * 16 + ((lane >> 3) & 1) * 8 + (lane & 7);
                int ch  = (kcol >> 3) + (lane >> 4);
                uint32_t off = swA(row, ch);
                ldsm_x4(ah[mf], aAh + off);
                ldsm_x4(al[mf], aAl + off);
            }
#pragma unroll
            for (int p = 0; p < 2; p++) {
                int k = kcol + ((lane >> 3) & 1) * 8 + (lane & 7);
                int n = warp_n * 32 + p * 16 + (lane >> 4) * 8;
                uint32_t off = swB(k, n >> 3);
                ldsm_x4_t(bh[p], aBh + off);
                ldsm_x4_t(bl[p], aBl + off);
            }
#pragma unroll
            for (int mf = 0; mf < 4; mf++)
#pragma unroll
                for (int nf = 0; nf < 4; nf++) {
                    const uint32_t* bph = &bh[nf >> 1][(nf & 1) * 2];
                    const uint32_t* bpl = &bl[nf >> 1][(nf & 1) * 2];
                    mma_bf16(acc[mf][nf], ah[mf], bph);
                    mma_bf16(acc[mf][nf], ah[mf], bpl);
                    mma_bf16(acc[mf][nf], al[mf], bph);
                }
        }
        __syncthreads();
        if (kt + 1 < nkt) {
            store();
            __syncthreads();
        }
    }

    // epilogue
#pragma unroll
    for (int mf = 0; mf < 4; mf++) {
        int r0 = m0 + warp_m * 64 + mf * 16 + (lane >> 2);
        float s0 = 1.f, t0 = 0.f, s1 = 1.f, t1 = 0.f;
        if (EPI) {
            float iv0 = rsqrtf(var[r0] + EPS_BN);
            s0 = gamma[r0] * iv0; t0 = beta[r0] - mean[r0] * s0;
            float iv1 = rsqrtf(var[r0 + 8] + EPS_BN);
            s1 = gamma[r0 + 8] * iv1; t1 = beta[r0 + 8] - mean[r0 + 8] * s1;
        }
#pragma unroll
        for (int nf = 0; nf < 4; nf++) {
            int c = n0 + warp_n * 32 + nf * 8 + (lane & 3) * 2;
            float* p0 = Cp + (size_t)r0 * N + c;
            float* p1 = Cp + (size_t)(r0 + 8) * N + c;
            float2 v0, v1;
            if (EPI) {
                v0 = make_float2(acc[mf][nf][0] * s0 + t0, acc[mf][nf][1] * s0 + t0);
                v1 = make_float2(acc[mf][nf][2] * s1 + t1, acc[mf][nf][3] * s1 + t1);
            } else {
                v0 = make_float2(acc[mf][nf][0], acc[mf][nf][1]);
                v1 = make_float2(acc[mf][nf][2], acc[mf][nf][3]);
            }
            *(float2*)p0 = v0;
            *(float2*)p1 = v1;
        }
    }
}

// ---------------------------------------------------------------------------
// Fused depthwise 5x5 (pad 2) + grouped 8x8 pointwise.
// ---------------------------------------------------------------------------
__global__ __launch_bounds__(256)
void dwpw_kernel(const float* __restrict__ qkv, const float* __restrict__ w_dw,
                 const float* __restrict__ w_pw, float* __restrict__ y)
{
    __shared__ float tile[8][12][36];
    __shared__ float wdw[8][25];
    __shared__ float wpw[64];

    const int b   = blockIdx.z / NGRP;
    const int g   = blockIdx.z % NGRP;
    const int ch0 = g * 8;
    const int w0  = blockIdx.x * 32;
    const int h0  = blockIdx.y * 8;
    const int tid = threadIdx.y * 32 + threadIdx.x;

    for (int i = tid; i < 200; i += 256)
        wdw[i / 25][i % 25] = w_dw[(ch0 + i / 25) * 25 + i % 25];
    if (tid < 64) wpw[tid] = w_pw[g * 64 + tid];

    const float* base = qkv + ((size_t)b * TD3 + ch0) * NPIX;
    for (int i = tid; i < 8 * 12 * 36; i += 256) {
        int c  = i / 432;
        int r  = (i % 432) / 36;
        int cc = i % 36;
        int gh = h0 - 2 + r;
        int gw = w0 - 2 + cc;
        float v = 0.f;
        if (gh >= 0 && gh < HH && gw >= 0 && gw < WW)
            v = base[(size_t)c * NPIX + gh * WW + gw];
        tile[c][r][cc] = v;
    }
    __syncthreads();

    const int tx = threadIdx.x, ty = threadIdx.y;
    float dw[8];
#pragma unroll
    for (int c = 0; c < 8; c++) {
        float s = 0.f;
#pragma unroll
        for (int i = 0; i < 5; i++)
#pragma unroll
            for (int j = 0; j < 5; j++)
                s += tile[c][ty + i][tx + j] * wdw[c][i * 5 + j];
        dw[c] = s;
    }

    const int n = (h0 + ty) * WW + (w0 + tx);
    float* obase = y + ((size_t)b * TD3 + ch0) * NPIX + n;
#pragma unroll
    for (int o = 0; o < 8; o++) {
        float s = 0.f;
#pragma unroll
        for (int i = 0; i < 8; i++) s += dw[i] * wpw[o * 8 + i];
        obase[(size_t)o * NPIX] = s;
    }
}

// ---------------------------------------------------------------------------
// Linear attention. One block per (batch, head). Emits bf16 hi/lo directly.
// ---------------------------------------------------------------------------
__global__ __launch_bounds__(256)
void attn_kernel(const float* __restrict__ qkv, const float* __restrict__ y,
                 __nv_bfloat16* __restrict__ att_h, __nv_bfloat16* __restrict__ att_l)
{
    const int bh = blockIdx.x;
    const int b  = bh / NHEAD;
    const int h  = bh % NHEAD;
    const int tid = threadIdx.x;

    const float* base = (h < 64)
        ? qkv + ((size_t)b * TD3 + h * 24) * NPIX
        : y   + ((size_t)b * TD3 + (h - 64) * 24) * NPIX;

    float acc[72];
#pragma unroll
    for (int i = 0; i < 72; i++) acc[i] = 0.f;

    for (int n = tid; n < NPIX; n += 256) {
        float kk[8], vv[8];
#pragma unroll
        for (int e = 0; e < 8; e++) kk[e] = fmaxf(base[(size_t)(8 + e) * NPIX + n], 0.f);
#pragma unroll
        for (int d = 0; d < 8; d++) vv[d] = base[(size_t)(16 + d) * NPIX + n];
#pragma unroll
        for (int d = 0; d < 8; d++)
#pragma unroll
            for (int e = 0; e < 8; e++) acc[d * 8 + e] += vv[d] * kk[e];
#pragma unroll
        for (int e = 0; e < 8; e++) acc[64 + e] += kk[e];
    }

    __shared__ float red[8][72];
    __shared__ float vk_s[72];
    const int lane = tid & 31, wid = tid >> 5;
#pragma unroll
    for (int i = 0; i < 72; i++) {
        float v = acc[i];
        v += __shfl_down_sync(0xffffffffu, v, 16);
        v += __shfl_down_sync(0xffffffffu, v, 8);
        v += __shfl_down_sync(0xffffffffu, v, 4);
        v += __shfl_down_sync(0xffffffffu, v, 2);
        v += __shfl_down_sync(0xffffffffu, v, 1);
        if (lane == 0) red[wid][i] = v;
    }
    __syncthreads();
    if (tid < 72) {
        float s = 0.f;
#pragma unroll
        for (int w = 0; w < 8; w++) s += red[w][tid];
        vk_s[tid] = s;
    }
    __syncthreads();

    float vk[72];
#pragma unroll
    for (int i = 0; i < 72; i++) vk[i] = vk_s[i];

    const size_t obase = ((size_t)b * 1024 + h * 8) * NPIX;
    for (int n = tid; n < NPIX; n += 256) {
        float q[8];
#pragma unroll
        for (int e = 0; e < 8; e++) q[e] = fmaxf(base[(size_t)e * NPIX + n], 0.f);
        float den = 0.f;
#pragma unroll
        for (int e = 0; e < 8; e++) den += vk[64 + e] * q[e];
        float inv = 1.f / (den + EPS_ATT);
#pragma unroll
        for (int d = 0; d < 8; d++) {
            float num = 0.f;
#pragma unroll
            for (int e = 0; e < 8; e++) num += vk[d * 8 + e] * q[e];
            float o = num * inv;
            __nv_bfloat16 hh = __float2bfloat16(o);
            size_t idx = obase + (size_t)d * NPIX + n;
            att_h[idx] = hh;
            att_l[idx] = __float2bfloat16(o - __bfloat162float(hh));
        }
    }
}

// ---------------------------------------------------------------------------
// Launch
// ---------------------------------------------------------------------------
extern "C" void kernel_launch(void* const* d_in, const int* in_sizes, int n_in,
                              void* d_out, int out_size)
{
    const float* x      = (const float*)d_in[0];
    const float* w_qkv  = (const float*)d_in[1];
    const float* w_dw   = (const float*)d_in[2];
    const float* w_pw   = (const float*)d_in[3];
    const float* w_proj = (const float*)d_in[4];
    const float* gamma  = (const float*)d_in[5];
    const float* beta   = (const float*)d_in[6];
    const float* mean   = (const float*)d_in[7];
    const float* var    = (const float*)d_in[8];
    float* out = (float*)d_out;

    float *qkv, *yb;
    __nv_bfloat16 *xh, *xl, *ath, *atl, *wqh, *wql, *wph, *wpl;
    cudaGetSymbolAddress((void**)&qkv, g_qkv);
    cudaGetSymbolAddress((void**)&yb,  g_y);
    cudaGetSymbolAddress((void**)&xh,  g_xh);
    cudaGetSymbolAddress((void**)&xl,  g_xl);
    cudaGetSymbolAddress((void**)&ath, g_atth);
    cudaGetSymbolAddress((void**)&atl, g_attl);
    cudaGetSymbolAddress((void**)&wqh, g_wqh);
    cudaGetSymbolAddress((void**)&wql, g_wql);
    cudaGetSymbolAddress((void**)&wph, g_wph);
    cudaGetSymbolAddress((void**)&wpl, g_wpl);

    // 0) bf16 hi/lo splits
    {
        int n4 = (B_SZ * C_IN * NPIX) / 4;
        split_kernel<<<(n4 + 255) / 256, 256>>>(x, xh, xl, n4);
        n4 = (TD3 * C_IN) / 4;
        split_kernel<<<(n4 + 255) / 256, 256>>>(w_qkv, wqh, wql, n4);
        n4 = (512 * 1024) / 4;
        split_kernel<<<(n4 + 255) / 256, 256>>>(w_proj, wph, wpl, n4);
    }

    // 1) qkv = w_qkv @ x   (M=1536, N=4096, K=512 per batch), fp32 out
    mma_gemm<false><<<dim3(NPIX / 128, TD3 / 128, B_SZ), 256>>>(
        wqh, wql, xh, xl, qkv, TD3, NPIX, C_IN,
        nullptr, nullptr, nullptr, nullptr);

    // 2) y = grouped-pw(dwconv5x5(qkv))
    dwpw_kernel<<<dim3(WW / 32, HH / 8, B_SZ * NGRP), dim3(32, 8)>>>(
        qkv, w_dw, w_pw, yb);

    // 3) linear attention -> att bf16 hi/lo (B,1024,4096)
    attn_kernel<<<B_SZ * NHEAD, 256>>>(qkv, yb, ath, atl);

    // 4) out = BN(w_proj @ att)  (M=512, N=4096, K=1024 per batch)
    mma_gemm<true><<<dim3(NPIX / 128, 512 / 128, B_SZ), 256>>>(
        wph, wpl, ath, atl, out, 512, NPIX, 1024,
        gamma, beta, mean, var);
}

// round 3
// speedup vs baseline: 2.1535x; 1.0208x over previous
#include <cuda_runtime.h>
#include <cuda_bf16.h>
#include <cstdint>
#include <cstddef>

// ---------------------------------------------------------------------------
// Problem constants
// ---------------------------------------------------------------------------
#define B_SZ   4
#define C_IN   512
#define TD3    1536          // 3*512
#define HH     64
#define WW     64
#define NPIX   4096          // 64*64
#define NGRP   192
#define NHEAD  128
#define EPS_ATT 1e-15f
#define EPS_BN  1e-5f

#define STAGES 3
#define STAGE_BYTES 32768    // 4 arrays x 8KB

// ---------------------------------------------------------------------------
// Scratch (device globals; no allocation allowed)
// ---------------------------------------------------------------------------
__device__ float          g_qkv [(size_t)B_SZ * TD3 * NPIX];     // 96 MB fp32
__device__ float          g_y   [(size_t)B_SZ * TD3 * NPIX];     // 96 MB fp32
__device__ __nv_bfloat16  g_xh  [(size_t)B_SZ * C_IN * NPIX];
__device__ __nv_bfloat16  g_xl  [(size_t)B_SZ * C_IN * NPIX];
__device__ __nv_bfloat16  g_atth[(size_t)B_SZ * 1024 * NPIX];
__device__ __nv_bfloat16  g_attl[(size_t)B_SZ * 1024 * NPIX];
__device__ __nv_bfloat16  g_wqh [TD3 * C_IN];
__device__ __nv_bfloat16  g_wql [TD3 * C_IN];
__device__ __nv_bfloat16  g_wph [512 * 1024];
__device__ __nv_bfloat16  g_wpl [512 * 1024];

// ---------------------------------------------------------------------------
// fp32 -> bf16 hi/lo split (vectorized x4)
// ---------------------------------------------------------------------------
__global__ void split_kernel(const float* __restrict__ in,
                             __nv_bfloat16* __restrict__ h,
                             __nv_bfloat16* __restrict__ l, int n4)
{
    int i = blockIdx.x * 256 + threadIdx.x;
    if (i >= n4) return;
    float4 v = ((const float4*)in)[i];
    __nv_bfloat16 h0 = __float2bfloat16(v.x);
    __nv_bfloat16 h1 = __float2bfloat16(v.y);
    __nv_bfloat16 h2 = __float2bfloat16(v.z);
    __nv_bfloat16 h3 = __float2bfloat16(v.w);
    __nv_bfloat162 hp0 = __nv_bfloat162(h0, h1), hp1 = __nv_bfloat162(h2, h3);
    __nv_bfloat162 lp0 = __nv_bfloat162(__float2bfloat16(v.x - __bfloat162float(h0)),
                                        __float2bfloat16(v.y - __bfloat162float(h1)));
    __nv_bfloat162 lp1 = __nv_bfloat162(__float2bfloat16(v.z - __bfloat162float(h2)),
                                        __float2bfloat16(v.w - __bfloat162float(h3)));
    ((__nv_bfloat162*)h)[i * 2]     = hp0;
    ((__nv_bfloat162*)h)[i * 2 + 1] = hp1;
    ((__nv_bfloat162*)l)[i * 2]     = lp0;
    ((__nv_bfloat162*)l)[i * 2 + 1] = lp1;
}

// ---------------------------------------------------------------------------
// mma / async helpers
// ---------------------------------------------------------------------------
__device__ __forceinline__ void ldsm_x4(uint32_t* r, uint32_t addr) {
    asm volatile("ldmatrix.sync.aligned.m8n8.x4.shared.b16 {%0,%1,%2,%3}, [%4];"
        : "=r"(r[0]), "=r"(r[1]), "=r"(r[2]), "=r"(r[3]) : "r"(addr));
}
__device__ __forceinline__ void ldsm_x4_t(uint32_t* r, uint32_t addr) {
    asm volatile("ldmatrix.sync.aligned.m8n8.x4.trans.shared.b16 {%0,%1,%2,%3}, [%4];"
        : "=r"(r[0]), "=r"(r[1]), "=r"(r[2]), "=r"(r[3]) : "r"(addr));
}
__device__ __forceinline__ void mma_bf16(float* c, const uint32_t* a, const uint32_t* b) {
    asm volatile("mma.sync.aligned.m16n8k16.row.col.f32.bf16.bf16.f32 "
        "{%0,%1,%2,%3}, {%4,%5,%6,%7}, {%8,%9}, {%0,%1,%2,%3};"
        : "+f"(c[0]), "+f"(c[1]), "+f"(c[2]), "+f"(c[3])
        : "r"(a[0]), "r"(a[1]), "r"(a[2]), "r"(a[3]), "r"(b[0]), "r"(b[1]));
}
__device__ __forceinline__ void cp16(uint32_t smem, const void* g) {
    asm volatile("cp.async.cg.shared.global [%0], [%1], 16;" :: "r"(smem), "l"(g));
}
__device__ __forceinline__ void cp_commit() {
    asm volatile("cp.async.commit_group;");
}
template <int N>
__device__ __forceinline__ void cp_wait() {
    asm volatile("cp.async.wait_group %0;" :: "n"(N));
}

// byte offsets within one 8KB array
__device__ __forceinline__ uint32_t swA(int row, int ch) {      // 128 rows x 64B
    return (uint32_t)(row * 64 + ((ch ^ ((row >> 1) & 3)) << 4));
}
__device__ __forceinline__ uint32_t swB(int k, int ch) {        // 32 rows x 256B
    return (uint32_t)(k * 256 + ((ch ^ (k & 7)) << 4));
}

// ---------------------------------------------------------------------------
// bf16-split tensor-core GEMM, 3-stage cp.async pipeline.
//   C[b] = (Ah+Al)(MxK) * (Bh+Bl)[b](KxN)  (3-term Markidis)
// Block 128x128, K-tile 32, 256 threads (8 warps, warp tile 64x32).
// ---------------------------------------------------------------------------
template <bool EPI>
__global__ __launch_bounds__(256, 1)
void mma_gemm(const __nv_bfloat16* __restrict__ Ah, const __nv_bfloat16* __restrict__ Al,
              const __nv_bfloat16* __restrict__ Bhg, const __nv_bfloat16* __restrict__ Blg,
              float* __restrict__ Cg, int M, int N, int K,
              const float* __restrict__ gamma, const float* __restrict__ beta,
              const float* __restrict__ mean,  const float* __restrict__ var)
{
    extern __shared__ __align__(16) char smem[];
    const uint32_t sbase = (uint32_t)__cvta_generic_to_shared(smem);

    const int tid  = threadIdx.x;
    const int lane = tid & 31;
    const int wid  = tid >> 5;
    const int warp_m = wid >> 2;
    const int warp_n = wid & 3;
    const int m0 = blockIdx.y * 128;
    const int n0 = blockIdx.x * 128;

    const __nv_bfloat16* Bh = Bhg + (size_t)blockIdx.z * K * N;
    const __nv_bfloat16* Bl = Blg + (size_t)blockIdx.z * K * N;
    float* Cp = Cg + (size_t)blockIdx.z * M * N;

    const int arow = tid >> 2, ach = tid & 3;
    const int bk   = tid >> 4, bch = tid & 15;

    float acc[4][4][4];
#pragma unroll
    for (int i = 0; i < 4; i++)
#pragma unroll
        for (int j = 0; j < 4; j++)
#pragma unroll
            for (int r = 0; r < 4; r++) acc[i][j][r] = 0.f;

    const int nkt = K / 32;

    auto prefetch = [&](int kt) {
        const uint32_t st = sbase + (kt % STAGES) * STAGE_BYTES;
#pragma unroll
        for (int i = 0; i < 2; i++) {
            size_t aoff = (size_t)(m0 + arow + i * 64) * K + kt * 32 + ach * 8;
            uint32_t ao = swA(arow + i * 64, ach);
            cp16(st + ao,        Ah + aoff);
            cp16(st + 8192 + ao, Al + aoff);
            size_t boff = (size_t)(kt * 32 + bk + i * 16) * N + n0 + bch * 8;
            uint32_t bo = swB(bk + i * 16, bch);
            cp16(st + 16384 + bo, Bh + boff);
            cp16(st + 24576 + bo, Bl + boff);
        }
        cp_commit();
    };

    prefetch(0);
    prefetch(1);

    for (int kt = 0; kt < nkt; ++kt) {
        cp_wait<STAGES - 2>();
        __syncthreads();

        if (kt + STAGES - 1 < nkt) prefetch(kt + STAGES - 1);
        else cp_commit();

        const uint32_t st  = sbase + (kt % STAGES) * STAGE_BYTES;
        const uint32_t aAh = st;
        const uint32_t aAl = st + 8192;
        const uint32_t aBh = st + 16384;
        const uint32_t aBl = st + 24576;

#pragma unroll
        for (int kk = 0; kk < 2; ++kk) {
            const int kcol = kk * 16;
            uint32_t ah[4][4], al[4][4], bh[2][4], bl[2][4];
#pragma unroll
            for (int mf = 0; mf < 4; mf++) {
                int row = warp_m * 64 + mf * 16 + ((lane >> 3) & 1) * 8 + (lane & 7);
                int ch  = (kcol >> 3) + (lane >> 4);
                uint32_t off = swA(row, ch);
                ldsm_x4(ah[mf], aAh + off);
                ldsm_x4(al[mf], aAl + off);
            }
#pragma unroll
            for (int p = 0; p < 2; p++) {
                int k = kcol + ((lane >> 3) & 1) * 8 + (lane & 7);
                int n = warp_n * 32 + p * 16 + (lane >> 4) * 8;
                uint32_t off = swB(k, n >> 3);
                ldsm_x4_t(bh[p], aBh + off);
                ldsm_x4_t(bl[p], aBl + off);
            }
#pragma unroll
            for (int mf = 0; mf < 4; mf++)
#pragma unroll
                for (int nf = 0; nf < 4; nf++) {
                    const uint32_t* bph = &bh[nf >> 1][(nf & 1) * 2];
                    const uint32_t* bpl = &bl[nf >> 1][(nf & 1) * 2];
                    mma_bf16(acc[mf][nf], ah[mf], bph);
                    mma_bf16(acc[mf][nf], ah[mf], bpl);
                    mma_bf16(acc[mf][nf], al[mf], bph);
                }
        }
        __syncthreads();
    }

    // epilogue
#pragma unroll
    for (int mf = 0; mf < 4; mf++) {
        int r0 = m0 + warp_m * 64 + mf * 16 + (lane >> 2);
        float s0 = 1.f, t0 = 0.f, s1 = 1.f, t1 = 0.f;
        if (EPI) {
            float iv0 = rsqrtf(var[r0] + EPS_BN);
            s0 = gamma[r0] * iv0; t0 = beta[r0] - mean[r0] * s0;
            float iv1 = rsqrtf(var[r0 + 8] + EPS_BN);
            s1 = gamma[r0 + 8] * iv1; t1 = beta[r0 + 8] - mean[r0 + 8] * s1;
        }
#pragma unroll
        for (int nf = 0; nf < 4; nf++) {
            int c = n0 + warp_n * 32 + nf * 8 + (lane & 3) * 2;
            float* p0 = Cp + (size_t)r0 * N + c;
            float* p1 = Cp + (size_t)(r0 + 8) * N + c;
            float2 v0, v1;
            if (EPI) {
                v0 = make_float2(acc[mf][nf][0] * s0 + t0, acc[mf][nf][1] * s0 + t0);
                v1 = make_float2(acc[mf][nf][2] * s1 + t1, acc[mf][nf][3] * s1 + t1);
            } else {
                v0 = make_float2(acc[mf][nf][0], acc[mf][nf][1]);
                v1 = make_float2(acc[mf][nf][2], acc[mf][nf][3]);
            }
            *(float2*)p0 = v0;
            *(float2*)p1 = v1;
        }
    }
}

// ---------------------------------------------------------------------------
// Fused depthwise 5x5 (pad 2) + grouped 8x8 pointwise.
// ---------------------------------------------------------------------------
__global__ __launch_bounds__(256)
void dwpw_kernel(const float* __restrict__ qkv, const float* __restrict__ w_dw,
                 const float* __restrict__ w_pw, float* __restrict__ y)
{
    __shared__ float tile[8][12][36];
    __shared__ float wdw[8][25];
    __shared__ float wpw[64];

    const int b   = blockIdx.z / NGRP;
    const int g   = blockIdx.z % NGRP;
    const int ch0 = g * 8;
    const int w0  = blockIdx.x * 32;
    const int h0  = blockIdx.y * 8;
    const int tid = threadIdx.y * 32 + threadIdx.x;

    for (int i = tid; i < 200; i += 256)
        wdw[i / 25][i % 25] = w_dw[(ch0 + i / 25) * 25 + i % 25];
    if (tid < 64) wpw[tid] = w_pw[g * 64 + tid];

    const float* base = qkv + ((size_t)b * TD3 + ch0) * NPIX;
    for (int i = tid; i < 8 * 12 * 36; i += 256) {
        int c  = i / 432;
        int r  = (i % 432) / 36;
        int cc = i % 36;
        int gh = h0 - 2 + r;
        int gw = w0 - 2 + cc;
        float v = 0.f;
        if (gh >= 0 && gh < HH && gw >= 0 && gw < WW)
            v = base[(size_t)c * NPIX + gh * WW + gw];
        tile[c][r][cc] = v;
    }
    __syncthreads();

    const int tx = threadIdx.x, ty = threadIdx.y;
    float dw[8];
#pragma unroll
    for (int c = 0; c < 8; c++) {
        float s = 0.f;
#pragma unroll
        for (int i = 0; i < 5; i++)
#pragma unroll
            for (int j = 0; j < 5; j++)
                s += tile[c][ty + i][tx + j] * wdw[c][i * 5 + j];
        dw[c] = s;
    }

    const int n = (h0 + ty) * WW + (w0 + tx);
    float* obase = y + ((size_t)b * TD3 + ch0) * NPIX + n;
#pragma unroll
    for (int o = 0; o < 8; o++) {
        float s = 0.f;
#pragma unroll
        for (int i = 0; i < 8; i++) s += dw[i] * wpw[o * 8 + i];
        obase[(size_t)o * NPIX] = s;
    }
}

// ---------------------------------------------------------------------------
// Linear attention. One block per (batch, head). Emits bf16 hi/lo directly.
// ---------------------------------------------------------------------------
__global__ __launch_bounds__(256)
void attn_kernel(const float* __restrict__ qkv, const float* __restrict__ y,
                 __nv_bfloat16* __restrict__ att_h, __nv_bfloat16* __restrict__ att_l)
{
    const int bh = blockIdx.x;
    const int b  = bh / NHEAD;
    const int h  = bh % NHEAD;
    const int tid = threadIdx.x;

    const float* base = (h < 64)
        ? qkv + ((size_t)b * TD3 + h * 24) * NPIX
        : y   + ((size_t)b * TD3 + (h - 64) * 24) * NPIX;

    float acc[72];
#pragma unroll
    for (int i = 0; i < 72; i++) acc[i] = 0.f;

    for (int n = tid; n < NPIX; n += 256) {
        float kk[8], vv[8];
#pragma unroll
        for (int e = 0; e < 8; e++) kk[e] = fmaxf(base[(size_t)(8 + e) * NPIX + n], 0.f);
#pragma unroll
        for (int d = 0; d < 8; d++) vv[d] = base[(size_t)(16 + d) * NPIX + n];
#pragma unroll
        for (int d = 0; d < 8; d++)
#pragma unroll
            for (int e = 0; e < 8; e++) acc[d * 8 + e] += vv[d] * kk[e];
#pragma unroll
        for (int e = 0; e < 8; e++) acc[64 + e] += kk[e];
    }

    __shared__ float red[8][72];
    __shared__ float vk_s[72];
    const int lane = tid & 31, wid = tid >> 5;
#pragma unroll
    for (int i = 0; i < 72; i++) {
        float v = acc[i];
        v += __shfl_down_sync(0xffffffffu, v, 16);
        v += __shfl_down_sync(0xffffffffu, v, 8);
        v += __shfl_down_sync(0xffffffffu, v, 4);
        v += __shfl_down_sync(0xffffffffu, v, 2);
        v += __shfl_down_sync(0xffffffffu, v, 1);
        if (lane == 0) red[wid][i] = v;
    }
    __syncthreads();
    if (tid < 72) {
        float s = 0.f;
#pragma unroll
        for (int w = 0; w < 8; w++) s += red[w][tid];
        vk_s[tid] = s;
    }
    __syncthreads();

    float vk[72];
#pragma unroll
    for (int i = 0; i < 72; i++) vk[i] = vk_s[i];

    const size_t obase = ((size_t)b * 1024 + h * 8) * NPIX;
    for (int n = tid; n < NPIX; n += 256) {
        float q[8];
#pragma unroll
        for (int e = 0; e < 8; e++) q[e] = fmaxf(base[(size_t)e * NPIX + n], 0.f);
        float den = 0.f;
#pragma unroll
        for (int e = 0; e < 8; e++) den += vk[64 + e] * q[e];
        float inv = 1.f / (den + EPS_ATT);
#pragma unroll
        for (int d = 0; d < 8; d++) {
            float num = 0.f;
#pragma unroll
            for (int e = 0; e < 8; e++) num += vk[d * 8 + e] * q[e];
            float o = num * inv;
            __nv_bfloat16 hh = __float2bfloat16(o);
            size_t idx = obase + (size_t)d * NPIX + n;
            att_h[idx] = hh;
            att_l[idx] = __float2bfloat16(o - __bfloat162float(hh));
        }
    }
}

// ---------------------------------------------------------------------------
// Launch
// ---------------------------------------------------------------------------
extern "C" void kernel_launch(void* const* d_in, const int* in_sizes, int n_in,
                              void* d_out, int out_size)
{
    const float* x      = (const float*)d_in[0];
    const float* w_qkv  = (const float*)d_in[1];
    const float* w_dw   = (const float*)d_in[2];
    const float* w_pw   = (const float*)d_in[3];
    const float* w_proj = (const float*)d_in[4];
    const float* gamma  = (const float*)d_in[5];
    const float* beta   = (const float*)d_in[6];
    const float* mean   = (const float*)d_in[7];
    const float* var    = (const float*)d_in[8];
    float* out = (float*)d_out;

    float *qkv, *yb;
    __nv_bfloat16 *xh, *xl, *ath, *atl, *wqh, *wql, *wph, *wpl;
    cudaGetSymbolAddress((void**)&qkv, g_qkv);
    cudaGetSymbolAddress((void**)&yb,  g_y);
    cudaGetSymbolAddress((void**)&xh,  g_xh);
    cudaGetSymbolAddress((void**)&xl,  g_xl);
    cudaGetSymbolAddress((void**)&ath, g_atth);
    cudaGetSymbolAddress((void**)&atl, g_attl);
    cudaGetSymbolAddress((void**)&wqh, g_wqh);
    cudaGetSymbolAddress((void**)&wql, g_wql);
    cudaGetSymbolAddress((void**)&wph, g_wph);
    cudaGetSymbolAddress((void**)&wpl, g_wpl);

    static int smem_set = 0;
    const int dyn_smem = STAGES * STAGE_BYTES;   // 96 KB
    if (!smem_set) {
        cudaFuncSetAttribute(mma_gemm<false>,
            cudaFuncAttributeMaxDynamicSharedMemorySize, dyn_smem);
        cudaFuncSetAttribute(mma_gemm<true>,
            cudaFuncAttributeMaxDynamicSharedMemorySize, dyn_smem);
        smem_set = 1;
    }

    // 0) bf16 hi/lo splits
    {
        int n4 = (B_SZ * C_IN * NPIX) / 4;
        split_kernel<<<(n4 + 255) / 256, 256>>>(x, xh, xl, n4);
        n4 = (TD3 * C_IN) / 4;
        split_kernel<<<(n4 + 255) / 256, 256>>>(w_qkv, wqh, wql, n4);
        n4 = (512 * 1024) / 4;
        split_kernel<<<(n4 + 255) / 256, 256>>>(w_proj, wph, wpl, n4);
    }

    // 1) qkv = w_qkv @ x   (M=1536, N=4096, K=512 per batch), fp32 out
    mma_gemm<false><<<dim3(NPIX / 128, TD3 / 128, B_SZ), 256, dyn_smem>>>(
        wqh, wql, xh, xl, qkv, TD3, NPIX, C_IN,
        nullptr, nullptr, nullptr, nullptr);

    // 2) y = grouped-pw(dwconv5x5(qkv))
    dwpw_kernel<<<dim3(WW / 32, HH / 8, B_SZ * NGRP), dim3(32, 8)>>>(
        qkv, w_dw, w_pw, yb);

    // 3) linear attention -> att bf16 hi/lo (B,1024,4096)
    attn_kernel<<<B_SZ * NHEAD, 256>>>(qkv, yb, ath, atl);

    // 4) out = BN(w_proj @ att)  (M=512, N=4096, K=1024 per batch)
    mma_gemm<true><<<dim3(NPIX / 128, 512 / 128, B_SZ), 256, dyn_smem>>>(
        wph, wpl, ath, atl, out, 512, NPIX, 1024,
        gamma, beta, mean, var);
}